// round 15
// baseline (speedup 1.0000x reference)
#include <cuda_runtime.h>
#include <math.h>

#define NB    16
#define NS    512
#define NBINS 511
#define NT    64              // col pair-group tiles (4 groups per block)
#define RROWS 4               // rows per block in row_fft

// Transposed row-FFT spectra: [sig][batch][pos][row]. sig0 = rowFFT(t),
// sig1 = rowFFT(z) - rowFFT(t) = rowFFT(z - t) by linearity. 67 MB.
__device__ float2 g_specT[2][NB][NS][NS];
// Global per-(sig,batch,bin) accumulators (float atomics). 64 KB.
__device__ float  g_acc[2][NB][512];
// Bin table [pos][k] with bit-reversal baked in. 512 KB.
__device__ unsigned short g_tab[NS * NS];
// Twiddle table, per-stage contiguous: segment for stage `half` starts at
// offset 512 - 2*half and holds W_{2*half}^j, j = 0..half-1.
__device__ float2 g_twk[512];

__device__ __forceinline__ unsigned brev9(unsigned x) { return __brev(x) >> 23; }

// ---------------- setup kernel (tab + twiddles + acc zeroing fused) ----------------

// bin = floor(511*sqrt(s2)/256) == largest b with 65536*b^2 <= 261121*s2.
// float sqrt estimate + exact integer fixup (bit-identical, no FP64).
__global__ void tab_kernel() {
    const int pos = blockIdx.x, k = threadIdx.x;
    const int du = (int)brev9(k)   - 256;
    const int dv = (int)brev9(pos) - 256;
    const int s2 = du * du + dv * dv;
    const long long rhs = 261121LL * (long long)s2;   // 511^2 * s2
    int bin = (int)(sqrtf((float)s2) * (511.0f / 256.0f));
    while ((long long)(bin + 1) * (bin + 1) * 65536LL <= rhs) bin++;
    while (bin > 0 && (long long)bin * bin * 65536LL > rhs) bin--;
    if (bin > 511) bin = 511;
    g_tab[pos * NS + k] = (unsigned short)bin;

    // Blocks 0..31 zero the accumulators (2*16*512 = 16384 floats).
    if (pos < 32) ((float*)g_acc)[pos * 512 + k] = 0.0f;

    if (pos == 0) {
        const int i = k;
#pragma unroll
        for (int half = 256; half >= 1; half >>= 1) {
            const int off = 512 - 2 * half;
            if (i >= off && i < off + half) {
                const int j = i - off;
                double ang = -6.283185307179586476925287 * (double)j / (double)(2 * half);
                g_twk[i] = make_float2((float)cos(ang), (float)sin(ang));
            }
        }
    }
}

// ---------------- FFT helpers ----------------

__device__ __forceinline__ float2 cadd(float2 a, float2 b) {
    return make_float2(a.x + b.x, a.y + b.y);
}
// (u - v) * tw
__device__ __forceinline__ float2 csubmul(float2 u, float2 v, float2 tw) {
    float dr = u.x - v.x, di = u.y - v.y;
    return make_float2(dr * tw.x - di * tw.y, dr * tw.y + di * tw.x);
}

// Two fused radix-2 DIF stage-layers (block sizes 4h then 2h) on one group of 4.
__device__ __forceinline__ void r4dif(float2 a, float2 b, float2 c, float2 d,
                                      float2 tw1, float2 tw1b, float2 tw2,
                                      float2& o0, float2& o1, float2& o2, float2& o3) {
    float2 t0 = cadd(a, c);
    float2 t1 = csubmul(a, c, tw1);
    float2 t2 = cadd(b, d);
    float2 t3 = csubmul(b, d, tw1b);
    o0 = cadd(t0, t2);
    o1 = csubmul(t0, t2, tw2);
    o2 = cadd(t1, t3);
    o3 = csubmul(t1, t3, tw2);
}

// Generic shuffle butterfly for half = 16, 8, 4.
__device__ __forceinline__ float2 bfly_shfl(float2 x, int half, float2 tw, int L) {
    float px = __shfl_xor_sync(0xffffffffu, x.x, half);
    float py = __shfl_xor_sync(0xffffffffu, x.y, half);
    if ((L & half) == 0)
        return make_float2(x.x + px, x.y + py);
    float dr = px - x.x, di = py - x.y;
    return make_float2(dr * tw.x - di * tw.y, dr * tw.y + di * tw.x);
}

// half = 2: twiddle is W_4^{L&1} = (1,0) or (0,-1) -> swap/negate.
__device__ __forceinline__ float2 bfly_h2(float2 x, int L) {
    float px = __shfl_xor_sync(0xffffffffu, x.x, 2);
    float py = __shfl_xor_sync(0xffffffffu, x.y, 2);
    if ((L & 2) == 0) return make_float2(x.x + px, x.y + py);
    float dr = px - x.x, di = py - x.y;
    return (L & 1) ? make_float2(di, -dr) : make_float2(dr, di);
}

// half = 1: plain add/sub.
__device__ __forceinline__ float2 bfly_h1(float2 x, int L) {
    float px = __shfl_xor_sync(0xffffffffu, x.x, 1);
    float py = __shfl_xor_sync(0xffffffffu, x.y, 1);
    if ((L & 1) == 0) return make_float2(x.x + px, x.y + py);
    return make_float2(px - x.x, py - x.y);
}

// Last 5 stages (half 16..1) for 4 register-resident points at positions
// pb, pb+32, pb+64, pb+96.
__device__ __forceinline__ void fft_reg_stages4(float2& x0, float2& x1,
                                                float2& x2, float2& x3,
                                                float2 tw16, float2 tw8, float2 tw4,
                                                int L) {
    x0 = bfly_shfl(x0, 16, tw16, L); x1 = bfly_shfl(x1, 16, tw16, L);
    x2 = bfly_shfl(x2, 16, tw16, L); x3 = bfly_shfl(x3, 16, tw16, L);
    x0 = bfly_shfl(x0, 8, tw8, L);   x1 = bfly_shfl(x1, 8, tw8, L);
    x2 = bfly_shfl(x2, 8, tw8, L);   x3 = bfly_shfl(x3, 8, tw8, L);
    x0 = bfly_shfl(x0, 4, tw4, L);   x1 = bfly_shfl(x1, 4, tw4, L);
    x2 = bfly_shfl(x2, 4, tw4, L);   x3 = bfly_shfl(x3, 4, tw4, L);
    x0 = bfly_h2(x0, L); x1 = bfly_h2(x1, L);
    x2 = bfly_h2(x2, L); x3 = bfly_h2(x3, L);
    x0 = bfly_h1(x0, L); x1 = bfly_h1(x1, L);
    x2 = bfly_h1(x2, L); x3 = bfly_h1(x3, L);
}

// ---------------- main kernels ----------------

// One block per (4-row tile, batch). 256 threads = 2 engines x 128
// (engine 0 -> t-row, engine 1 -> z-row; linearity subtraction at write-out).
// The stage buffer IS the exchange buffer: pass A scatters into stage[f][r];
// pass B reads it and writes its results back to its own slots (each slot is
// read by exactly one thread -> no barrier between pass-B read and write).
// 36 KB smem -> 6 blocks/SM; ONE barrier per row.
__global__ __launch_bounds__(256, 6) void row_fft_kernel(const float* __restrict__ z,
                                                         const float* __restrict__ tt) {
    __shared__ float2 stage[2][RROWS][NS];  // [engine][row][pos] 32 KB
    __shared__ float2 s_tw[512];            // 4 KB
    const int rt = blockIdx.x, b = blockIdx.y;
    const int t = threadIdx.x;
    const int f = t >> 7;          // engine: 0 -> t-row, 1 -> z-row
    const int g = t & 127;
    const int L = t & 31;
    const int ww = g >> 5;
    const int pb = 128 * ww + L;

    s_tw[t]       = g_twk[t];
    s_tw[t + 256] = g_twk[t + 256];

    const float* __restrict__ srcbase = (f == 0) ? tt : z;
    bool first = true;

#pragma unroll
    for (int r = 0; r < RROWS; r++) {
        const int row = rt * RROWS + r;
        const float2* __restrict__ sp =
            (const float2*)srcbase + ((size_t)b * NS + row) * NS;

        float2 a0 = __ldcs(&sp[g]),       a1 = __ldcs(&sp[g + 128]);
        float2 a2 = __ldcs(&sp[g + 256]), a3 = __ldcs(&sp[g + 384]);
        if (first) { __syncthreads(); first = false; }   // s_tw ready

        float2 o0, o1, o2, o3;
        r4dif(a0, a1, a2, a3, s_tw[g], s_tw[g + 128], s_tw[256 + g], o0, o1, o2, o3);
        float2* wf = &stage[f][r][0];
        wf[g] = o0; wf[g + 128] = o1; wf[g + 256] = o2; wf[g + 384] = o3;
        __syncthreads();                         // pass-A scatter visible

        float2 b0 = wf[pb], b1 = wf[pb + 32], b2 = wf[pb + 64], b3 = wf[pb + 96];
        float2 x0, x1, x2, x3;
        r4dif(b0, b1, b2, b3, s_tw[384 + L], s_tw[416 + L], s_tw[448 + L],
              x0, x1, x2, x3);
        fft_reg_stages4(x0, x1, x2, x3,
                        s_tw[480 + (L & 15)], s_tw[496 + (L & 7)], s_tw[504 + (L & 3)],
                        L);

        // In-place store to this thread's own pass-B slots (no barrier needed).
        wf[pb]      = x0;
        wf[pb + 32] = x1;
        wf[pb + 64] = x2;
        wf[pb + 96] = x3;
    }
    __syncthreads();                             // stage complete for write-out

    // Transposed write-out (32B sectors). sig 0 = stage[0] (Ft);
    // sig 1 = stage[1] - stage[0] (Fz - Ft = rowFFT(z - t) by linearity).
#pragma unroll
    for (int k = 0; k < 4; k++) {
        const int i   = t + k * 256;
        const int fo  = i >> 9;
        const int pos = i & 511;
        float2 s0 = stage[fo][0][pos];
        float2 s1 = stage[fo][1][pos];
        float2 s2 = stage[fo][2][pos];
        float2 s3 = stage[fo][3][pos];
        if (fo == 1) {
            float2 q0 = stage[0][0][pos], q1 = stage[0][1][pos];
            float2 q2 = stage[0][2][pos], q3 = stage[0][3][pos];
            s0 = make_float2(s0.x - q0.x, s0.y - q0.y);
            s1 = make_float2(s1.x - q1.x, s1.y - q1.y);
            s2 = make_float2(s2.x - q2.x, s2.y - q2.y);
            s3 = make_float2(s3.x - q3.x, s3.y - q3.y);
        }
        float4* dst = (float4*)&g_specT[fo][b][pos][rt * RROWS];
        dst[0] = make_float4(s0.x, s0.y, s1.x, s1.y);
        dst[1] = make_float4(s2.x, s2.y, s3.x, s3.y);
    }
}

// One block per (4 pair-groups, batch, sig). 256 threads = 2 column engines.
// Proven R11 core: radial-symmetry pairing (one atomic per point pair) +
// cp.async 2-deep ring. Final flush goes straight to g_acc via global
// float atomics (reduction tree stage 1 eliminated).
__global__ __launch_bounds__(256) void col_fft_kernel() {
    __shared__ __align__(16) float2 in[3][2][NS];  // ring [buf][engine][pos] 24 KB
    __shared__ float  bins[512];                   // 2 KB
    const int bx = blockIdx.x, b = blockIdx.y, sig = blockIdx.z;
    const int t = threadIdx.x;
    const int f = t >> 7;
    const int g = t & 127;
    const int L = t & 31;
    const int ww = g >> 5;
    const int pb = 128 * ww + L;

    bins[t]       = 0.0f;
    bins[t + 256] = 0.0f;

    // Loop-invariant twiddles in registers.
    const float2 twA0 = g_twk[g],       twA1 = g_twk[g + 128], twA2 = g_twk[256 + g];
    const float2 twB0 = g_twk[384 + L], twB1 = g_twk[416 + L], twB2 = g_twk[448 + L];
    const float2 tw16 = g_twk[480 + (L & 15)];
    const float2 tw8  = g_twk[496 + (L & 7)];
    const float2 tw4  = g_twk[504 + (L & 3)];

    // Column sequence per engine: A(grp0), B(grp0), A(grp1), B(grp1).
    auto pos_of = [&](int it) -> int {
        const int grp = 4 * bx + 2 * f + (it >> 1);
        const bool isB = (it & 1) != 0;
        if (grp == 255) return isB ? 1 : 0;             // self-paired dv=0 / dv=-256
        return isB ? (int)brev9(511 - grp) : (int)brev9(grp + 1);
    };

    auto prefetch = [&](int it, int buf_idx) {
        if (it < 4) {
            const int pos = pos_of(it);
            const float4* src = (const float4*)&g_specT[sig][b][pos][0];
            unsigned dst = (unsigned)__cvta_generic_to_shared(&in[buf_idx][f][0]);
            asm volatile("cp.async.cg.shared.global [%0], [%1], 16;"
                         :: "r"(dst + g * 16), "l"(src + g) : "memory");
            asm volatile("cp.async.cg.shared.global [%0], [%1], 16;"
                         :: "r"(dst + g * 16 + 2048), "l"(src + g + 128) : "memory");
        }
        asm volatile("cp.async.commit_group;" ::: "memory");
    };

    prefetch(0, 0);
    prefetch(1, 1);

    float pw0 = 0.0f, pw1 = 0.0f, pw2 = 0.0f, pw3 = 0.0f;

#pragma unroll
    for (int it = 0; it < 4; it++) {
        asm volatile("cp.async.wait_group 1;" ::: "memory");
        __syncthreads();                    // data visible; prev buf reads done
        prefetch(it + 2, (it + 2) % 3);     // refill the buffer freed last iter

        float2* buf = &in[it % 3][f][0];

        // Pass A (half = 256,128): in-place on thread-private slots.
        float2 a0 = buf[g], a1 = buf[g + 128], a2 = buf[g + 256], a3 = buf[g + 384];
        float2 o0, o1, o2, o3;
        r4dif(a0, a1, a2, a3, twA0, twA1, twA2, o0, o1, o2, o3);
        buf[g] = o0; buf[g + 128] = o1; buf[g + 256] = o2; buf[g + 384] = o3;
        __syncthreads();

        // Pass B (half = 64,32) + register shuffle tail.
        float2 b0 = buf[pb], b1 = buf[pb + 32], b2 = buf[pb + 64], b3 = buf[pb + 96];
        float2 x0, x1, x2, x3;
        r4dif(b0, b1, b2, b3, twB0, twB1, twB2, x0, x1, x2, x3);
        fft_reg_stages4(x0, x1, x2, x3, tw16, tw8, tw4, L);

        float p0 = x0.x * x0.x + x0.y * x0.y;
        float p1 = x1.x * x1.x + x1.y * x1.y;
        float p2 = x2.x * x2.x + x2.y * x2.y;
        float p3 = x3.x * x3.x + x3.y * x3.y;

        const int  grp     = 4 * bx + 2 * f + (it >> 1);
        const bool isB     = (it & 1) != 0;
        const bool special = (grp == 255);
        if (!isB && !special) {
            pw0 = p0; pw1 = p1; pw2 = p2; pw3 = p3;   // stash A-half powers
        } else {
            if (!special) { p0 += pw0; p1 += pw1; p2 += pw2; p3 += pw3; }
            const int pos = pos_of(it);
            const unsigned short* __restrict__ tb = &g_tab[pos * NS];
            atomicAdd(&bins[tb[pb]],      p0);
            atomicAdd(&bins[tb[pb + 32]], p1);
            atomicAdd(&bins[tb[pb + 64]], p2);
            atomicAdd(&bins[tb[pb + 96]], p3);
        }
    }
    __syncthreads();

    atomicAdd(&g_acc[sig][b][t],       bins[t]);
    atomicAdd(&g_acc[sig][b][t + 256], bins[t + 256]);
}

// ---------------- final reduction (single block) ----------------

__global__ __launch_bounds__(512) void reduce_final_kernel(float* __restrict__ out) {
    __shared__ double sh[512];
    const int t = threadIdx.x;
    double acc = 0.0;
#pragma unroll
    for (int b = 0; b < NB; b++) {
        float ns = g_acc[0][b][t];
        float es = g_acc[1][b][t];
        if (t < NBINS) acc += (double)es / fmax((double)ns, 1e-8);
    }
    sh[t] = acc;
    __syncthreads();
    for (int k = 256; k > 0; k >>= 1) {
        if (t < k) sh[t] += sh[t + k];
        __syncthreads();
    }
    if (t == 0) out[0] = (float)(sh[0] / (double)NB);
}

extern "C" void kernel_launch(void* const* d_in, const int* in_sizes, int n_in,
                              void* d_out, int out_size) {
    const float* z  = (const float*)d_in[0];   // z_ [16,512,512,2]
    const float* tt = (const float*)d_in[1];   // t_ [16,512,512,2]
    float* out = (float*)d_out;
    (void)in_sizes; (void)n_in; (void)out_size;

    tab_kernel<<<NS, NS>>>();                  // tab + twiddles + acc zeroing
    {
        dim3 grid(NS / RROWS, NB);
        row_fft_kernel<<<grid, 256>>>(z, tt);
    }
    {
        dim3 grid(NT, NB, 2);
        col_fft_kernel<<<grid, 256>>>();
    }
    reduce_final_kernel<<<1, 512>>>(out);
}

// round 16
// speedup vs baseline: 1.1457x; 1.1457x over previous
#include <cuda_runtime.h>
#include <math.h>

#define NB    16
#define NS    512
#define NBINS 511
#define NT    64              // col pair-group tiles (4 groups per block)
#define RROWS 4               // rows per block in row_fft

// Transposed row-FFT spectra: [sig][batch][pos][row]. sig0 = rowFFT(t),
// sig1 = rowFFT(z) - rowFFT(t) = rowFFT(z - t) by linearity. 67 MB.
__device__ float2 g_specT[2][NB][NS][NS];
// Global per-(sig,batch,bin) accumulators (float atomics). 64 KB.
__device__ float  g_acc[2][NB][512];
// Bin table [pos][k] with bit-reversal baked in. 512 KB.
__device__ unsigned short g_tab[NS * NS];
// Twiddle table, per-stage contiguous: segment for stage `half` starts at
// offset 512 - 2*half and holds W_{2*half}^j, j = 0..half-1.
__device__ float2 g_twk[512];
__device__ double g_bsum[NB];

__device__ __forceinline__ unsigned brev9(unsigned x) { return __brev(x) >> 23; }

// ---------------- setup kernel (tab + twiddles + acc zeroing fused) ----------------

// bin = floor(511*sqrt(s2)/256) == largest b with 65536*b^2 <= 261121*s2.
// float sqrt estimate + exact integer fixup (bit-identical, no FP64).
__global__ void tab_kernel() {
    const int pos = blockIdx.x, k = threadIdx.x;
    const int du = (int)brev9(k)   - 256;
    const int dv = (int)brev9(pos) - 256;
    const int s2 = du * du + dv * dv;
    const long long rhs = 261121LL * (long long)s2;   // 511^2 * s2
    int bin = (int)(sqrtf((float)s2) * (511.0f / 256.0f));
    while ((long long)(bin + 1) * (bin + 1) * 65536LL <= rhs) bin++;
    while (bin > 0 && (long long)bin * bin * 65536LL > rhs) bin--;
    if (bin > 511) bin = 511;
    g_tab[pos * NS + k] = (unsigned short)bin;

    // Blocks 0..31 zero the accumulators (2*16*512 = 16384 floats).
    if (pos < 32) ((float*)g_acc)[pos * 512 + k] = 0.0f;

    if (pos == 0) {
        const int i = k;
#pragma unroll
        for (int half = 256; half >= 1; half >>= 1) {
            const int off = 512 - 2 * half;
            if (i >= off && i < off + half) {
                const int j = i - off;
                double ang = -6.283185307179586476925287 * (double)j / (double)(2 * half);
                g_twk[i] = make_float2((float)cos(ang), (float)sin(ang));
            }
        }
    }
}

// ---------------- FFT helpers ----------------

__device__ __forceinline__ float2 cadd(float2 a, float2 b) {
    return make_float2(a.x + b.x, a.y + b.y);
}
// (u - v) * tw
__device__ __forceinline__ float2 csubmul(float2 u, float2 v, float2 tw) {
    float dr = u.x - v.x, di = u.y - v.y;
    return make_float2(dr * tw.x - di * tw.y, dr * tw.y + di * tw.x);
}

// Two fused radix-2 DIF stage-layers (block sizes 4h then 2h) on one group of 4.
__device__ __forceinline__ void r4dif(float2 a, float2 b, float2 c, float2 d,
                                      float2 tw1, float2 tw1b, float2 tw2,
                                      float2& o0, float2& o1, float2& o2, float2& o3) {
    float2 t0 = cadd(a, c);
    float2 t1 = csubmul(a, c, tw1);
    float2 t2 = cadd(b, d);
    float2 t3 = csubmul(b, d, tw1b);
    o0 = cadd(t0, t2);
    o1 = csubmul(t0, t2, tw2);
    o2 = cadd(t1, t3);
    o3 = csubmul(t1, t3, tw2);
}

// Generic shuffle butterfly for half = 16, 8, 4.
__device__ __forceinline__ float2 bfly_shfl(float2 x, int half, float2 tw, int L) {
    float px = __shfl_xor_sync(0xffffffffu, x.x, half);
    float py = __shfl_xor_sync(0xffffffffu, x.y, half);
    if ((L & half) == 0)
        return make_float2(x.x + px, x.y + py);
    float dr = px - x.x, di = py - x.y;
    return make_float2(dr * tw.x - di * tw.y, dr * tw.y + di * tw.x);
}

// half = 2: twiddle is W_4^{L&1} = (1,0) or (0,-1) -> swap/negate.
__device__ __forceinline__ float2 bfly_h2(float2 x, int L) {
    float px = __shfl_xor_sync(0xffffffffu, x.x, 2);
    float py = __shfl_xor_sync(0xffffffffu, x.y, 2);
    if ((L & 2) == 0) return make_float2(x.x + px, x.y + py);
    float dr = px - x.x, di = py - x.y;
    return (L & 1) ? make_float2(di, -dr) : make_float2(dr, di);
}

// half = 1: plain add/sub.
__device__ __forceinline__ float2 bfly_h1(float2 x, int L) {
    float px = __shfl_xor_sync(0xffffffffu, x.x, 1);
    float py = __shfl_xor_sync(0xffffffffu, x.y, 1);
    if ((L & 1) == 0) return make_float2(x.x + px, x.y + py);
    return make_float2(px - x.x, py - x.y);
}

// Last 5 stages (half 16..1) for 4 register-resident points at positions
// pb, pb+32, pb+64, pb+96.
__device__ __forceinline__ void fft_reg_stages4(float2& x0, float2& x1,
                                                float2& x2, float2& x3,
                                                float2 tw16, float2 tw8, float2 tw4,
                                                int L) {
    x0 = bfly_shfl(x0, 16, tw16, L); x1 = bfly_shfl(x1, 16, tw16, L);
    x2 = bfly_shfl(x2, 16, tw16, L); x3 = bfly_shfl(x3, 16, tw16, L);
    x0 = bfly_shfl(x0, 8, tw8, L);   x1 = bfly_shfl(x1, 8, tw8, L);
    x2 = bfly_shfl(x2, 8, tw8, L);   x3 = bfly_shfl(x3, 8, tw8, L);
    x0 = bfly_shfl(x0, 4, tw4, L);   x1 = bfly_shfl(x1, 4, tw4, L);
    x2 = bfly_shfl(x2, 4, tw4, L);   x3 = bfly_shfl(x3, 4, tw4, L);
    x0 = bfly_h2(x0, L); x1 = bfly_h2(x1, L);
    x2 = bfly_h2(x2, L); x3 = bfly_h2(x3, L);
    x0 = bfly_h1(x0, L); x1 = bfly_h1(x1, L);
    x2 = bfly_h1(x2, L); x3 = bfly_h1(x3, L);
}

// ---------------- main kernels ----------------

// One block per (4-row tile, batch). 256 threads = 2 engines x 128
// (engine 0 -> t-row, engine 1 -> z-row; linearity subtraction at write-out).
// The stage buffer IS the exchange buffer: pass A scatters into stage[f][r];
// pass B reads it and writes its results back to its own slots (each slot is
// read by exactly one thread -> no barrier between pass-B read and write).
// 36 KB smem -> 6 blocks/SM; ONE barrier per row.
__global__ __launch_bounds__(256, 6) void row_fft_kernel(const float* __restrict__ z,
                                                         const float* __restrict__ tt) {
    __shared__ float2 stage[2][RROWS][NS];  // [engine][row][pos] 32 KB
    __shared__ float2 s_tw[512];            // 4 KB
    const int rt = blockIdx.x, b = blockIdx.y;
    const int t = threadIdx.x;
    const int f = t >> 7;          // engine: 0 -> t-row, 1 -> z-row
    const int g = t & 127;
    const int L = t & 31;
    const int ww = g >> 5;
    const int pb = 128 * ww + L;

    s_tw[t]       = g_twk[t];
    s_tw[t + 256] = g_twk[t + 256];

    const float* __restrict__ srcbase = (f == 0) ? tt : z;
    bool first = true;

#pragma unroll
    for (int r = 0; r < RROWS; r++) {
        const int row = rt * RROWS + r;
        const float2* __restrict__ sp =
            (const float2*)srcbase + ((size_t)b * NS + row) * NS;

        float2 a0 = __ldcs(&sp[g]),       a1 = __ldcs(&sp[g + 128]);
        float2 a2 = __ldcs(&sp[g + 256]), a3 = __ldcs(&sp[g + 384]);
        if (first) { __syncthreads(); first = false; }   // s_tw ready

        float2 o0, o1, o2, o3;
        r4dif(a0, a1, a2, a3, s_tw[g], s_tw[g + 128], s_tw[256 + g], o0, o1, o2, o3);
        float2* wf = &stage[f][r][0];
        wf[g] = o0; wf[g + 128] = o1; wf[g + 256] = o2; wf[g + 384] = o3;
        __syncthreads();                         // pass-A scatter visible

        float2 b0 = wf[pb], b1 = wf[pb + 32], b2 = wf[pb + 64], b3 = wf[pb + 96];
        float2 x0, x1, x2, x3;
        r4dif(b0, b1, b2, b3, s_tw[384 + L], s_tw[416 + L], s_tw[448 + L],
              x0, x1, x2, x3);
        fft_reg_stages4(x0, x1, x2, x3,
                        s_tw[480 + (L & 15)], s_tw[496 + (L & 7)], s_tw[504 + (L & 3)],
                        L);

        // In-place store to this thread's own pass-B slots (no barrier needed).
        wf[pb]      = x0;
        wf[pb + 32] = x1;
        wf[pb + 64] = x2;
        wf[pb + 96] = x3;
    }
    __syncthreads();                             // stage complete for write-out

    // Transposed write-out (32B sectors). sig 0 = stage[0] (Ft);
    // sig 1 = stage[1] - stage[0] (Fz - Ft = rowFFT(z - t) by linearity).
#pragma unroll
    for (int k = 0; k < 4; k++) {
        const int i   = t + k * 256;
        const int fo  = i >> 9;
        const int pos = i & 511;
        float2 s0 = stage[fo][0][pos];
        float2 s1 = stage[fo][1][pos];
        float2 s2 = stage[fo][2][pos];
        float2 s3 = stage[fo][3][pos];
        if (fo == 1) {
            float2 q0 = stage[0][0][pos], q1 = stage[0][1][pos];
            float2 q2 = stage[0][2][pos], q3 = stage[0][3][pos];
            s0 = make_float2(s0.x - q0.x, s0.y - q0.y);
            s1 = make_float2(s1.x - q1.x, s1.y - q1.y);
            s2 = make_float2(s2.x - q2.x, s2.y - q2.y);
            s3 = make_float2(s3.x - q3.x, s3.y - q3.y);
        }
        float4* dst = (float4*)&g_specT[fo][b][pos][rt * RROWS];
        dst[0] = make_float4(s0.x, s0.y, s1.x, s1.y);
        dst[1] = make_float4(s2.x, s2.y, s3.x, s3.y);
    }
}

// One block per (4 pair-groups, batch, sig). 256 threads = 2 column engines.
// Proven R11 core: radial-symmetry pairing (one atomic per point pair) +
// cp.async 2-deep ring. Final flush goes straight to g_acc via global
// float atomics.
__global__ __launch_bounds__(256) void col_fft_kernel() {
    __shared__ __align__(16) float2 in[3][2][NS];  // ring [buf][engine][pos] 24 KB
    __shared__ float  bins[512];                   // 2 KB
    const int bx = blockIdx.x, b = blockIdx.y, sig = blockIdx.z;
    const int t = threadIdx.x;
    const int f = t >> 7;
    const int g = t & 127;
    const int L = t & 31;
    const int ww = g >> 5;
    const int pb = 128 * ww + L;

    bins[t]       = 0.0f;
    bins[t + 256] = 0.0f;

    // Loop-invariant twiddles in registers.
    const float2 twA0 = g_twk[g],       twA1 = g_twk[g + 128], twA2 = g_twk[256 + g];
    const float2 twB0 = g_twk[384 + L], twB1 = g_twk[416 + L], twB2 = g_twk[448 + L];
    const float2 tw16 = g_twk[480 + (L & 15)];
    const float2 tw8  = g_twk[496 + (L & 7)];
    const float2 tw4  = g_twk[504 + (L & 3)];

    // Column sequence per engine: A(grp0), B(grp0), A(grp1), B(grp1).
    auto pos_of = [&](int it) -> int {
        const int grp = 4 * bx + 2 * f + (it >> 1);
        const bool isB = (it & 1) != 0;
        if (grp == 255) return isB ? 1 : 0;             // self-paired dv=0 / dv=-256
        return isB ? (int)brev9(511 - grp) : (int)brev9(grp + 1);
    };

    auto prefetch = [&](int it, int buf_idx) {
        if (it < 4) {
            const int pos = pos_of(it);
            const float4* src = (const float4*)&g_specT[sig][b][pos][0];
            unsigned dst = (unsigned)__cvta_generic_to_shared(&in[buf_idx][f][0]);
            asm volatile("cp.async.cg.shared.global [%0], [%1], 16;"
                         :: "r"(dst + g * 16), "l"(src + g) : "memory");
            asm volatile("cp.async.cg.shared.global [%0], [%1], 16;"
                         :: "r"(dst + g * 16 + 2048), "l"(src + g + 128) : "memory");
        }
        asm volatile("cp.async.commit_group;" ::: "memory");
    };

    prefetch(0, 0);
    prefetch(1, 1);

    float pw0 = 0.0f, pw1 = 0.0f, pw2 = 0.0f, pw3 = 0.0f;

#pragma unroll
    for (int it = 0; it < 4; it++) {
        asm volatile("cp.async.wait_group 1;" ::: "memory");
        __syncthreads();                    // data visible; prev buf reads done
        prefetch(it + 2, (it + 2) % 3);     // refill the buffer freed last iter

        float2* buf = &in[it % 3][f][0];

        // Pass A (half = 256,128): in-place on thread-private slots.
        float2 a0 = buf[g], a1 = buf[g + 128], a2 = buf[g + 256], a3 = buf[g + 384];
        float2 o0, o1, o2, o3;
        r4dif(a0, a1, a2, a3, twA0, twA1, twA2, o0, o1, o2, o3);
        buf[g] = o0; buf[g + 128] = o1; buf[g + 256] = o2; buf[g + 384] = o3;
        __syncthreads();

        // Pass B (half = 64,32) + register shuffle tail.
        float2 b0 = buf[pb], b1 = buf[pb + 32], b2 = buf[pb + 64], b3 = buf[pb + 96];
        float2 x0, x1, x2, x3;
        r4dif(b0, b1, b2, b3, twB0, twB1, twB2, x0, x1, x2, x3);
        fft_reg_stages4(x0, x1, x2, x3, tw16, tw8, tw4, L);

        float p0 = x0.x * x0.x + x0.y * x0.y;
        float p1 = x1.x * x1.x + x1.y * x1.y;
        float p2 = x2.x * x2.x + x2.y * x2.y;
        float p3 = x3.x * x3.x + x3.y * x3.y;

        const int  grp     = 4 * bx + 2 * f + (it >> 1);
        const bool isB     = (it & 1) != 0;
        const bool special = (grp == 255);
        if (!isB && !special) {
            pw0 = p0; pw1 = p1; pw2 = p2; pw3 = p3;   // stash A-half powers
        } else {
            if (!special) { p0 += pw0; p1 += pw1; p2 += pw2; p3 += pw3; }
            const int pos = pos_of(it);
            const unsigned short* __restrict__ tb = &g_tab[pos * NS];
            atomicAdd(&bins[tb[pb]],      p0);
            atomicAdd(&bins[tb[pb + 32]], p1);
            atomicAdd(&bins[tb[pb + 64]], p2);
            atomicAdd(&bins[tb[pb + 96]], p3);
        }
    }
    __syncthreads();

    atomicAdd(&g_acc[sig][b][t],       bins[t]);
    atomicAdd(&g_acc[sig][b][t + 256], bins[t + 256]);
}

// ---------------- final reduction (FP64 divides spread across 16 SMs) ----------------

__global__ __launch_bounds__(512) void reduce_batch_kernel() {
    __shared__ double sh[512];
    const int b = blockIdx.x, t = threadIdx.x;
    double v = 0.0;
    if (t < NBINS) {
        double ns = (double)g_acc[0][b][t];
        double es = (double)g_acc[1][b][t];
        v = es / fmax(ns, 1e-8);
    }
    sh[t] = v;
    __syncthreads();
    for (int k = 256; k > 0; k >>= 1) {
        if (t < k) sh[t] += sh[t + k];
        __syncthreads();
    }
    if (t == 0) g_bsum[b] = sh[0];
}

__global__ void reduce2_kernel(float* __restrict__ out) {
    double s = 0.0;
#pragma unroll
    for (int i = 0; i < NB; i++) s += g_bsum[i];
    out[0] = (float)(s / (double)NB);
}

extern "C" void kernel_launch(void* const* d_in, const int* in_sizes, int n_in,
                              void* d_out, int out_size) {
    const float* z  = (const float*)d_in[0];   // z_ [16,512,512,2]
    const float* tt = (const float*)d_in[1];   // t_ [16,512,512,2]
    float* out = (float*)d_out;
    (void)in_sizes; (void)n_in; (void)out_size;

    tab_kernel<<<NS, NS>>>();                  // tab + twiddles + acc zeroing
    {
        dim3 grid(NS / RROWS, NB);
        row_fft_kernel<<<grid, 256>>>(z, tt);
    }
    {
        dim3 grid(NT, NB, 2);
        col_fft_kernel<<<grid, 256>>>();
    }
    reduce_batch_kernel<<<NB, 512>>>();
    reduce2_kernel<<<1, 1>>>(out);
}

// round 17
// speedup vs baseline: 1.1551x; 1.0083x over previous
#include <cuda_runtime.h>
#include <math.h>

#define NB    16
#define NS    512
#define NBINS 511
#define NT    64              // col pair-group tiles (4 groups per block)
#define RROWS 4               // rows per block in row_fft

// Transposed row-FFT spectra: [sig][batch][pos][row]. sig0 = rowFFT(t),
// sig1 = rowFFT(z) - rowFFT(t) = rowFFT(z - t) by linearity. 67 MB.
__device__ float2 g_specT[2][NB][NS][NS];
// Global per-(sig,batch,bin) accumulators (float atomics). 64 KB.
__device__ float  g_acc[2][NB][512];
// Bin table [pos][slot], PERMUTED so col threads load one ushort4:
// slot = 4*g + c for output position k = 128*(g>>5) + 32*c + (g&31). 512 KB.
__device__ unsigned short g_tab[NS * NS];
// Twiddle table, per-stage contiguous: segment for stage `half` starts at
// offset 512 - 2*half and holds W_{2*half}^j, j = 0..half-1.
__device__ float2 g_twk[512];
__device__ double g_bsum[NB];

__device__ __forceinline__ unsigned brev9(unsigned x) { return __brev(x) >> 23; }

// ---------------- setup kernel (tab + twiddles + acc zeroing fused) ----------------

// bin = floor(511*sqrt(s2)/256) == largest b with 65536*b^2 <= 261121*s2.
// float sqrt estimate + exact integer fixup (bit-identical, no FP64).
__global__ void tab_kernel() {
    const int pos = blockIdx.x, k = threadIdx.x;
    const int du = (int)brev9(k)   - 256;
    const int dv = (int)brev9(pos) - 256;
    const int s2 = du * du + dv * dv;
    const long long rhs = 261121LL * (long long)s2;   // 511^2 * s2
    int bin = (int)(sqrtf((float)s2) * (511.0f / 256.0f));
    while ((long long)(bin + 1) * (bin + 1) * 65536LL <= rhs) bin++;
    while (bin > 0 && (long long)bin * bin * 65536LL > rhs) bin--;
    if (bin > 511) bin = 511;
    // Permuted slot: k = 128*ww + 32*c + L -> g = 32*ww + L, slot = 4*g + c.
    const int ww = k >> 7, c = (k >> 5) & 3, L = k & 31;
    const int slot = 4 * (32 * ww + L) + c;
    g_tab[pos * NS + slot] = (unsigned short)bin;

    // Blocks 0..31 zero the accumulators (2*16*512 = 16384 floats).
    if (pos < 32) ((float*)g_acc)[pos * 512 + k] = 0.0f;

    if (pos == 0) {
        const int i = k;
#pragma unroll
        for (int half = 256; half >= 1; half >>= 1) {
            const int off = 512 - 2 * half;
            if (i >= off && i < off + half) {
                const int j = i - off;
                double ang = -6.283185307179586476925287 * (double)j / (double)(2 * half);
                g_twk[i] = make_float2((float)cos(ang), (float)sin(ang));
            }
        }
    }
}

// ---------------- FFT helpers ----------------

__device__ __forceinline__ float2 cadd(float2 a, float2 b) {
    return make_float2(a.x + b.x, a.y + b.y);
}
// (u - v) * tw
__device__ __forceinline__ float2 csubmul(float2 u, float2 v, float2 tw) {
    float dr = u.x - v.x, di = u.y - v.y;
    return make_float2(dr * tw.x - di * tw.y, dr * tw.y + di * tw.x);
}

// Two fused radix-2 DIF stage-layers (block sizes 4h then 2h) on one group of 4.
__device__ __forceinline__ void r4dif(float2 a, float2 b, float2 c, float2 d,
                                      float2 tw1, float2 tw1b, float2 tw2,
                                      float2& o0, float2& o1, float2& o2, float2& o3) {
    float2 t0 = cadd(a, c);
    float2 t1 = csubmul(a, c, tw1);
    float2 t2 = cadd(b, d);
    float2 t3 = csubmul(b, d, tw1b);
    o0 = cadd(t0, t2);
    o1 = csubmul(t0, t2, tw2);
    o2 = cadd(t1, t3);
    o3 = csubmul(t1, t3, tw2);
}

// Generic shuffle butterfly for half = 16, 8, 4.
__device__ __forceinline__ float2 bfly_shfl(float2 x, int half, float2 tw, int L) {
    float px = __shfl_xor_sync(0xffffffffu, x.x, half);
    float py = __shfl_xor_sync(0xffffffffu, x.y, half);
    if ((L & half) == 0)
        return make_float2(x.x + px, x.y + py);
    float dr = px - x.x, di = py - x.y;
    return make_float2(dr * tw.x - di * tw.y, dr * tw.y + di * tw.x);
}

// half = 2: twiddle is W_4^{L&1} = (1,0) or (0,-1) -> swap/negate.
__device__ __forceinline__ float2 bfly_h2(float2 x, int L) {
    float px = __shfl_xor_sync(0xffffffffu, x.x, 2);
    float py = __shfl_xor_sync(0xffffffffu, x.y, 2);
    if ((L & 2) == 0) return make_float2(x.x + px, x.y + py);
    float dr = px - x.x, di = py - x.y;
    return (L & 1) ? make_float2(di, -dr) : make_float2(dr, di);
}

// half = 1: plain add/sub.
__device__ __forceinline__ float2 bfly_h1(float2 x, int L) {
    float px = __shfl_xor_sync(0xffffffffu, x.x, 1);
    float py = __shfl_xor_sync(0xffffffffu, x.y, 1);
    if ((L & 1) == 0) return make_float2(x.x + px, x.y + py);
    return make_float2(px - x.x, py - x.y);
}

// Last 5 stages (half 16..1) for 4 register-resident points at positions
// pb, pb+32, pb+64, pb+96.
__device__ __forceinline__ void fft_reg_stages4(float2& x0, float2& x1,
                                                float2& x2, float2& x3,
                                                float2 tw16, float2 tw8, float2 tw4,
                                                int L) {
    x0 = bfly_shfl(x0, 16, tw16, L); x1 = bfly_shfl(x1, 16, tw16, L);
    x2 = bfly_shfl(x2, 16, tw16, L); x3 = bfly_shfl(x3, 16, tw16, L);
    x0 = bfly_shfl(x0, 8, tw8, L);   x1 = bfly_shfl(x1, 8, tw8, L);
    x2 = bfly_shfl(x2, 8, tw8, L);   x3 = bfly_shfl(x3, 8, tw8, L);
    x0 = bfly_shfl(x0, 4, tw4, L);   x1 = bfly_shfl(x1, 4, tw4, L);
    x2 = bfly_shfl(x2, 4, tw4, L);   x3 = bfly_shfl(x3, 4, tw4, L);
    x0 = bfly_h2(x0, L); x1 = bfly_h2(x1, L);
    x2 = bfly_h2(x2, L); x3 = bfly_h2(x3, L);
    x0 = bfly_h1(x0, L); x1 = bfly_h1(x1, L);
    x2 = bfly_h1(x2, L); x3 = bfly_h1(x3, L);
}

// ---------------- main kernels ----------------

// One block per (4-row tile, batch). 256 threads = 2 engines x 128
// (engine 0 -> t-row, engine 1 -> z-row; linearity subtraction at write-out).
// Stage buffer doubles as exchange buffer; ONE barrier per row.
__global__ __launch_bounds__(256, 6) void row_fft_kernel(const float* __restrict__ z,
                                                         const float* __restrict__ tt) {
    __shared__ float2 stage[2][RROWS][NS];  // [engine][row][pos] 32 KB
    __shared__ float2 s_tw[512];            // 4 KB
    const int rt = blockIdx.x, b = blockIdx.y;
    const int t = threadIdx.x;
    const int f = t >> 7;          // engine: 0 -> t-row, 1 -> z-row
    const int g = t & 127;
    const int L = t & 31;
    const int ww = g >> 5;
    const int pb = 128 * ww + L;

    s_tw[t]       = g_twk[t];
    s_tw[t + 256] = g_twk[t + 256];

    const float* __restrict__ srcbase = (f == 0) ? tt : z;
    bool first = true;

#pragma unroll
    for (int r = 0; r < RROWS; r++) {
        const int row = rt * RROWS + r;
        const float2* __restrict__ sp =
            (const float2*)srcbase + ((size_t)b * NS + row) * NS;

        float2 a0 = __ldcs(&sp[g]),       a1 = __ldcs(&sp[g + 128]);
        float2 a2 = __ldcs(&sp[g + 256]), a3 = __ldcs(&sp[g + 384]);
        if (first) { __syncthreads(); first = false; }   // s_tw ready

        float2 o0, o1, o2, o3;
        r4dif(a0, a1, a2, a3, s_tw[g], s_tw[g + 128], s_tw[256 + g], o0, o1, o2, o3);
        float2* wf = &stage[f][r][0];
        wf[g] = o0; wf[g + 128] = o1; wf[g + 256] = o2; wf[g + 384] = o3;
        __syncthreads();                         // pass-A scatter visible

        float2 b0 = wf[pb], b1 = wf[pb + 32], b2 = wf[pb + 64], b3 = wf[pb + 96];
        float2 x0, x1, x2, x3;
        r4dif(b0, b1, b2, b3, s_tw[384 + L], s_tw[416 + L], s_tw[448 + L],
              x0, x1, x2, x3);
        fft_reg_stages4(x0, x1, x2, x3,
                        s_tw[480 + (L & 15)], s_tw[496 + (L & 7)], s_tw[504 + (L & 3)],
                        L);

        // In-place store to this thread's own pass-B slots (no barrier needed).
        wf[pb]      = x0;
        wf[pb + 32] = x1;
        wf[pb + 64] = x2;
        wf[pb + 96] = x3;
    }
    __syncthreads();                             // stage complete for write-out

    // Transposed write-out (32B sectors). Each thread handles one pos for BOTH
    // sigs: stage[0] read once, both streams written (8 LDS + 4 STG per pos).
#pragma unroll
    for (int k = 0; k < 2; k++) {
        const int pos = t + k * 256;
        float2 a0 = stage[0][0][pos], a1 = stage[0][1][pos];
        float2 a2 = stage[0][2][pos], a3 = stage[0][3][pos];
        float2 c0 = stage[1][0][pos], c1 = stage[1][1][pos];
        float2 c2 = stage[1][2][pos], c3 = stage[1][3][pos];
        float4* dst0 = (float4*)&g_specT[0][b][pos][rt * RROWS];
        dst0[0] = make_float4(a0.x, a0.y, a1.x, a1.y);
        dst0[1] = make_float4(a2.x, a2.y, a3.x, a3.y);
        float4* dst1 = (float4*)&g_specT[1][b][pos][rt * RROWS];
        dst1[0] = make_float4(c0.x - a0.x, c0.y - a0.y, c1.x - a1.x, c1.y - a1.y);
        dst1[1] = make_float4(c2.x - a2.x, c2.y - a2.y, c3.x - a3.x, c3.y - a3.y);
    }
}

// One block per (4 pair-groups, batch, sig). 256 threads = 2 column engines.
// Proven R11 core: radial-symmetry pairing (one atomic per point pair) +
// cp.async 2-deep ring + direct g_acc flush. Bin table now ushort4-packed.
__global__ __launch_bounds__(256) void col_fft_kernel() {
    __shared__ __align__(16) float2 in[3][2][NS];  // ring [buf][engine][pos] 24 KB
    __shared__ float  bins[512];                   // 2 KB
    const int bx = blockIdx.x, b = blockIdx.y, sig = blockIdx.z;
    const int t = threadIdx.x;
    const int f = t >> 7;
    const int g = t & 127;
    const int L = t & 31;
    const int ww = g >> 5;
    const int pb = 128 * ww + L;

    bins[t]       = 0.0f;
    bins[t + 256] = 0.0f;

    // Loop-invariant twiddles in registers.
    const float2 twA0 = g_twk[g],       twA1 = g_twk[g + 128], twA2 = g_twk[256 + g];
    const float2 twB0 = g_twk[384 + L], twB1 = g_twk[416 + L], twB2 = g_twk[448 + L];
    const float2 tw16 = g_twk[480 + (L & 15)];
    const float2 tw8  = g_twk[496 + (L & 7)];
    const float2 tw4  = g_twk[504 + (L & 3)];

    // Column sequence per engine: A(grp0), B(grp0), A(grp1), B(grp1).
    auto pos_of = [&](int it) -> int {
        const int grp = 4 * bx + 2 * f + (it >> 1);
        const bool isB = (it & 1) != 0;
        if (grp == 255) return isB ? 1 : 0;             // self-paired dv=0 / dv=-256
        return isB ? (int)brev9(511 - grp) : (int)brev9(grp + 1);
    };

    auto prefetch = [&](int it, int buf_idx) {
        if (it < 4) {
            const int pos = pos_of(it);
            const float4* src = (const float4*)&g_specT[sig][b][pos][0];
            unsigned dst = (unsigned)__cvta_generic_to_shared(&in[buf_idx][f][0]);
            asm volatile("cp.async.cg.shared.global [%0], [%1], 16;"
                         :: "r"(dst + g * 16), "l"(src + g) : "memory");
            asm volatile("cp.async.cg.shared.global [%0], [%1], 16;"
                         :: "r"(dst + g * 16 + 2048), "l"(src + g + 128) : "memory");
        }
        asm volatile("cp.async.commit_group;" ::: "memory");
    };

    prefetch(0, 0);
    prefetch(1, 1);

    float pw0 = 0.0f, pw1 = 0.0f, pw2 = 0.0f, pw3 = 0.0f;

#pragma unroll
    for (int it = 0; it < 4; it++) {
        asm volatile("cp.async.wait_group 1;" ::: "memory");
        __syncthreads();                    // data visible; prev buf reads done
        prefetch(it + 2, (it + 2) % 3);     // refill the buffer freed last iter

        float2* buf = &in[it % 3][f][0];

        // Pass A (half = 256,128): in-place on thread-private slots.
        float2 a0 = buf[g], a1 = buf[g + 128], a2 = buf[g + 256], a3 = buf[g + 384];
        float2 o0, o1, o2, o3;
        r4dif(a0, a1, a2, a3, twA0, twA1, twA2, o0, o1, o2, o3);
        buf[g] = o0; buf[g + 128] = o1; buf[g + 256] = o2; buf[g + 384] = o3;
        __syncthreads();

        // Pass B (half = 64,32) + register shuffle tail.
        float2 b0 = buf[pb], b1 = buf[pb + 32], b2 = buf[pb + 64], b3 = buf[pb + 96];
        float2 x0, x1, x2, x3;
        r4dif(b0, b1, b2, b3, twB0, twB1, twB2, x0, x1, x2, x3);
        fft_reg_stages4(x0, x1, x2, x3, tw16, tw8, tw4, L);

        float p0 = x0.x * x0.x + x0.y * x0.y;
        float p1 = x1.x * x1.x + x1.y * x1.y;
        float p2 = x2.x * x2.x + x2.y * x2.y;
        float p3 = x3.x * x3.x + x3.y * x3.y;

        const int  grp     = 4 * bx + 2 * f + (it >> 1);
        const bool isB     = (it & 1) != 0;
        const bool special = (grp == 255);
        if (!isB && !special) {
            pw0 = p0; pw1 = p1; pw2 = p2; pw3 = p3;   // stash A-half powers
        } else {
            if (!special) { p0 += pw0; p1 += pw1; p2 += pw2; p3 += pw3; }
            // One aligned 8-byte load: this thread's 4 bins (packed layout).
            const int pos = pos_of(it);
            const ushort4 tv = *(const ushort4*)&g_tab[pos * NS + 4 * g];
            atomicAdd(&bins[tv.x], p0);
            atomicAdd(&bins[tv.y], p1);
            atomicAdd(&bins[tv.z], p2);
            atomicAdd(&bins[tv.w], p3);
        }
    }
    __syncthreads();

    atomicAdd(&g_acc[sig][b][t],       bins[t]);
    atomicAdd(&g_acc[sig][b][t + 256], bins[t + 256]);
}

// ---------------- final reduction (FP64 divides spread across 16 SMs) ----------------

__global__ __launch_bounds__(512) void reduce_batch_kernel() {
    __shared__ double sh[512];
    const int b = blockIdx.x, t = threadIdx.x;
    double v = 0.0;
    if (t < NBINS) {
        double ns = (double)g_acc[0][b][t];
        double es = (double)g_acc[1][b][t];
        v = es / fmax(ns, 1e-8);
    }
    sh[t] = v;
    __syncthreads();
    for (int k = 256; k > 0; k >>= 1) {
        if (t < k) sh[t] += sh[t + k];
        __syncthreads();
    }
    if (t == 0) g_bsum[b] = sh[0];
}

__global__ void reduce2_kernel(float* __restrict__ out) {
    double s = 0.0;
#pragma unroll
    for (int i = 0; i < NB; i++) s += g_bsum[i];
    out[0] = (float)(s / (double)NB);
}

extern "C" void kernel_launch(void* const* d_in, const int* in_sizes, int n_in,
                              void* d_out, int out_size) {
    const float* z  = (const float*)d_in[0];   // z_ [16,512,512,2]
    const float* tt = (const float*)d_in[1];   // t_ [16,512,512,2]
    float* out = (float*)d_out;
    (void)in_sizes; (void)n_in; (void)out_size;

    tab_kernel<<<NS, NS>>>();                  // tab + twiddles + acc zeroing
    {
        dim3 grid(NS / RROWS, NB);
        row_fft_kernel<<<grid, 256>>>(z, tt);
    }
    {
        dim3 grid(NT, NB, 2);
        col_fft_kernel<<<grid, 256>>>();
    }
    reduce_batch_kernel<<<NB, 512>>>();
    reduce2_kernel<<<1, 1>>>(out);
}